// round 2
// baseline (speedup 1.0000x reference)
#include <cuda_runtime.h>
#include <cuda_bf16.h>
#include <math.h>

#define H 1024
#define I 2048
#define E 8
#define T 4096
#define TOPK 2

// out layout: [0, T*H) routed ; [T*H] aux ; [T*H+1] z ; [T*H+2, +T*E) logits
#define OUT_AUX   (T*H)
#define OUT_Z     (T*H + 1)
#define OUT_LOG   (T*H + 2)

// ---------------- device scratch (allocation-free contract) ----------------
__device__ int   g_count[E];
__device__ int   g_tok[E][T];
__device__ float g_wt[E][T];
__device__ float g_probs[T * E];
__device__ float g_z[T];
__device__ float g_inter[(size_t)E * T * I];       // expert SwiGLU intermediate
__device__ float g_shared_inter[(size_t)T * I];    // shared-expert intermediate

__device__ __forceinline__ float silu(float v) {
    return v / (1.0f + expf(-v));
}

// ---------------- init ----------------
__global__ void init_kernel() {
    int i = threadIdx.x;
    if (i < E) g_count[i] = 0;
}

// ---------------- router: logits, softmax, top-2, lists, loss partials ----
__global__ void router_kernel(const float* __restrict__ x,
                              const float* __restrict__ rw,
                              float* __restrict__ out_logits) {
    int t = blockIdx.x;
    int tid = threadIdx.x;                 // 256 threads
    const float* xr = x + (size_t)t * H;

    float p[E];
#pragma unroll
    for (int e = 0; e < E; e++) p[e] = 0.0f;

    for (int h = tid; h < H; h += 256) {
        float xv = xr[h];
        const float* r = rw + (size_t)h * E;
#pragma unroll
        for (int e = 0; e < E; e++) p[e] += xv * r[e];
    }

    // warp reduce
#pragma unroll
    for (int off = 16; off > 0; off >>= 1) {
#pragma unroll
        for (int e = 0; e < E; e++)
            p[e] += __shfl_down_sync(0xFFFFFFFFu, p[e], off);
    }

    __shared__ float sred[8][E];
    int warp = tid >> 5, lane = tid & 31;
    if (lane == 0) {
#pragma unroll
        for (int e = 0; e < E; e++) sred[warp][e] = p[e];
    }
    __syncthreads();

    if (tid == 0) {
        float logit[E];
#pragma unroll
        for (int e = 0; e < E; e++) {
            float s = 0.0f;
#pragma unroll
            for (int w = 0; w < 8; w++) s += sred[w][e];
            logit[e] = s;
            out_logits[(size_t)t * E + e] = s;
        }
        float mx = logit[0];
#pragma unroll
        for (int e = 1; e < E; e++) mx = fmaxf(mx, logit[e]);
        float se = 0.0f, pr[E];
#pragma unroll
        for (int e = 0; e < E; e++) { pr[e] = expf(logit[e] - mx); se += pr[e]; }
        float inv = 1.0f / se;
#pragma unroll
        for (int e = 0; e < E; e++) {
            pr[e] *= inv;
            g_probs[(size_t)t * E + e] = pr[e];
        }
        float lse = mx + logf(se);
        g_z[t] = lse * lse;

        // top-2 (lowest index wins ties, matching jax top_k)
        int i0 = 0;
#pragma unroll
        for (int e = 1; e < E; e++) if (pr[e] > pr[i0]) i0 = e;
        int i1 = (i0 == 0) ? 1 : 0;
#pragma unroll
        for (int e = 0; e < E; e++)
            if (e != i0 && pr[e] > pr[i1]) i1 = e;

        float w0 = pr[i0], w1 = pr[i1];
        float ws = 1.0f / (w0 + w1);
        w0 *= ws; w1 *= ws;

        int s0 = atomicAdd(&g_count[i0], 1);
        g_tok[i0][s0] = t; g_wt[i0][s0] = w0;
        int s1 = atomicAdd(&g_count[i1], 1);
        g_tok[i1][s1] = t; g_wt[i1][s1] = w1;
    }
}

// ---------------- GEMM1: inter = silu(X@G) * (X@U) ----------------
// 64x64 tile, BK=16, 256 threads, 4x4 microtile (x2 for gate/up)
__global__ void gemm1_kernel(const float* __restrict__ x,
                             const float* __restrict__ gw,
                             const float* __restrict__ uw,
                             int shared_mode) {
    int e   = shared_mode ? 0 : blockIdx.z;
    int cnt = shared_mode ? T : g_count[e];
    int m0  = blockIdx.y * 64;
    if (m0 >= cnt) return;
    int n0 = blockIdx.x * 64;

    size_t woff = shared_mode ? 0 : (size_t)e * H * I;
    float* inter = shared_mode ? g_shared_inter : (g_inter + (size_t)e * T * I);

    __shared__ float As[16][64];
    __shared__ float Bg[16][64];
    __shared__ float Bu[16][64];

    int tid = threadIdx.x;
    int tx = tid & 15, ty = tid >> 4;

    int a_row = tid >> 2;
    int a_k   = (tid & 3) * 4;
    int r_load = m0 + a_row;
    const float* xrow = nullptr;
    if (r_load < cnt) {
        int token = shared_mode ? r_load : g_tok[e][r_load];
        xrow = x + (size_t)token * H;
    }
    int b_k = tid >> 4;
    int b_j = (tid & 15) * 4;

    float accG[4][4], accU[4][4];
#pragma unroll
    for (int i = 0; i < 4; i++)
#pragma unroll
        for (int j = 0; j < 4; j++) { accG[i][j] = 0.0f; accU[i][j] = 0.0f; }

    for (int k0 = 0; k0 < H; k0 += 16) {
        float4 av = make_float4(0.f, 0.f, 0.f, 0.f);
        if (xrow) av = *reinterpret_cast<const float4*>(xrow + k0 + a_k);
        As[a_k + 0][a_row] = av.x;
        As[a_k + 1][a_row] = av.y;
        As[a_k + 2][a_row] = av.z;
        As[a_k + 3][a_row] = av.w;

        const float4* gp = reinterpret_cast<const float4*>(gw + woff + (size_t)(k0 + b_k) * I + n0 + b_j);
        const float4* up = reinterpret_cast<const float4*>(uw + woff + (size_t)(k0 + b_k) * I + n0 + b_j);
        *reinterpret_cast<float4*>(&Bg[b_k][b_j]) = *gp;
        *reinterpret_cast<float4*>(&Bu[b_k][b_j]) = *up;
        __syncthreads();

#pragma unroll
        for (int kk = 0; kk < 16; kk++) {
            float4 a4 = *reinterpret_cast<const float4*>(&As[kk][ty * 4]);
            float4 g4 = *reinterpret_cast<const float4*>(&Bg[kk][tx * 4]);
            float4 u4 = *reinterpret_cast<const float4*>(&Bu[kk][tx * 4]);
            float a[4] = {a4.x, a4.y, a4.z, a4.w};
            float g[4] = {g4.x, g4.y, g4.z, g4.w};
            float u[4] = {u4.x, u4.y, u4.z, u4.w};
#pragma unroll
            for (int ii = 0; ii < 4; ii++)
#pragma unroll
                for (int jj = 0; jj < 4; jj++) {
                    accG[ii][jj] += a[ii] * g[jj];
                    accU[ii][jj] += a[ii] * u[jj];
                }
        }
        __syncthreads();
    }

#pragma unroll
    for (int ii = 0; ii < 4; ii++) {
        int rr = m0 + ty * 4 + ii;
        if (rr < cnt) {
            float4 o;
            o.x = silu(accG[ii][0]) * accU[ii][0];
            o.y = silu(accG[ii][1]) * accU[ii][1];
            o.z = silu(accG[ii][2]) * accU[ii][2];
            o.w = silu(accG[ii][3]) * accU[ii][3];
            *reinterpret_cast<float4*>(inter + (size_t)rr * I + n0 + tx * 4) = o;
        }
    }
}

// ---------------- GEMM2: routed += w * (inter @ D) ----------------
__global__ void gemm2_kernel(const float* __restrict__ dw,
                             float* __restrict__ routed,
                             int shared_mode) {
    int e   = shared_mode ? 0 : blockIdx.z;
    int cnt = shared_mode ? T : g_count[e];
    int m0  = blockIdx.y * 64;
    if (m0 >= cnt) return;
    int n0 = blockIdx.x * 64;

    size_t woff = shared_mode ? 0 : (size_t)e * I * H;
    const float* inter = shared_mode ? g_shared_inter : (g_inter + (size_t)e * T * I);

    __shared__ float As[16][64];
    __shared__ float Bd[16][64];

    int tid = threadIdx.x;
    int tx = tid & 15, ty = tid >> 4;

    int a_row = tid >> 2;
    int a_k   = (tid & 3) * 4;
    int r_load = m0 + a_row;
    const float* arow = (r_load < cnt) ? (inter + (size_t)r_load * I) : nullptr;

    int b_k = tid >> 4;
    int b_j = (tid & 15) * 4;

    float acc[4][4];
#pragma unroll
    for (int i = 0; i < 4; i++)
#pragma unroll
        for (int j = 0; j < 4; j++) acc[i][j] = 0.0f;

    for (int k0 = 0; k0 < I; k0 += 16) {
        float4 av = make_float4(0.f, 0.f, 0.f, 0.f);
        if (arow) av = *reinterpret_cast<const float4*>(arow + k0 + a_k);
        As[a_k + 0][a_row] = av.x;
        As[a_k + 1][a_row] = av.y;
        As[a_k + 2][a_row] = av.z;
        As[a_k + 3][a_row] = av.w;

        const float4* dp = reinterpret_cast<const float4*>(dw + woff + (size_t)(k0 + b_k) * H + n0 + b_j);
        *reinterpret_cast<float4*>(&Bd[b_k][b_j]) = *dp;
        __syncthreads();

#pragma unroll
        for (int kk = 0; kk < 16; kk++) {
            float4 a4 = *reinterpret_cast<const float4*>(&As[kk][ty * 4]);
            float4 b4 = *reinterpret_cast<const float4*>(&Bd[kk][tx * 4]);
            float a[4] = {a4.x, a4.y, a4.z, a4.w};
            float b[4] = {b4.x, b4.y, b4.z, b4.w};
#pragma unroll
            for (int ii = 0; ii < 4; ii++)
#pragma unroll
                for (int jj = 0; jj < 4; jj++)
                    acc[ii][jj] += a[ii] * b[jj];
        }
        __syncthreads();
    }

#pragma unroll
    for (int ii = 0; ii < 4; ii++) {
        int rr = m0 + ty * 4 + ii;
        if (rr >= cnt) continue;
        if (shared_mode) {
            // first writer of routed: plain store (covers every [t, h])
            float4 o = make_float4(acc[ii][0], acc[ii][1], acc[ii][2], acc[ii][3]);
            *reinterpret_cast<float4*>(routed + (size_t)rr * H + n0 + tx * 4) = o;
        } else {
            int token = g_tok[e][rr];
            float w = g_wt[e][rr];
            float* dst = routed + (size_t)token * H + n0 + tx * 4;
            atomicAdd(dst + 0, w * acc[ii][0]);
            atomicAdd(dst + 1, w * acc[ii][1]);
            atomicAdd(dst + 2, w * acc[ii][2]);
            atomicAdd(dst + 3, w * acc[ii][3]);
        }
    }
}

// ---------------- finalize losses ----------------
__global__ void finalize_kernel(float* __restrict__ out) {
    int tid = threadIdx.x;   // 256
    float ps[E];
#pragma unroll
    for (int e = 0; e < E; e++) ps[e] = 0.0f;
    float zs = 0.0f;
    for (int t = tid; t < T; t += 256) {
        zs += g_z[t];
#pragma unroll
        for (int e = 0; e < E; e++) ps[e] += g_probs[(size_t)t * E + e];
    }
#pragma unroll
    for (int off = 16; off > 0; off >>= 1) {
        zs += __shfl_down_sync(0xFFFFFFFFu, zs, off);
#pragma unroll
        for (int e = 0; e < E; e++)
            ps[e] += __shfl_down_sync(0xFFFFFFFFu, ps[e], off);
    }
    __shared__ float sp[8][E];
    __shared__ float sz[8];
    int warp = tid >> 5, lane = tid & 31;
    if (lane == 0) {
        sz[warp] = zs;
#pragma unroll
        for (int e = 0; e < E; e++) sp[warp][e] = ps[e];
    }
    __syncthreads();
    if (tid == 0) {
        float ztot = 0.0f;
        float ptot[E];
#pragma unroll
        for (int e = 0; e < E; e++) ptot[e] = 0.0f;
#pragma unroll
        for (int w = 0; w < 8; w++) {
            ztot += sz[w];
#pragma unroll
            for (int e = 0; e < E; e++) ptot[e] += sp[w][e];
        }
        float aux = 0.0f;
#pragma unroll
        for (int e = 0; e < E; e++) {
            float tpe = 0.5f * (float)g_count[e] / (float)T;
            float ppe = ptot[e] / (float)T;
            aux += tpe * ppe;
        }
        out[OUT_AUX] = (float)E * aux;
        out[OUT_Z]   = ztot / (float)T;
    }
}

// ---------------- launch ----------------
extern "C" void kernel_launch(void* const* d_in, const int* in_sizes, int n_in,
                              void* d_out, int out_size) {
    const float* x  = (const float*)d_in[0];
    const float* rw = (const float*)d_in[1];
    const float* gw = (const float*)d_in[2];
    const float* uw = (const float*)d_in[3];
    const float* dw = (const float*)d_in[4];
    const float* sg = (const float*)d_in[5];
    const float* su = (const float*)d_in[6];
    const float* sd = (const float*)d_in[7];
    float* out = (float*)d_out;

    init_kernel<<<1, 32>>>();
    router_kernel<<<T, 256>>>(x, rw, out + OUT_LOG);

    // shared expert (dense, all tokens); its GEMM2 plain-writes routed
    gemm1_kernel<<<dim3(I / 64, T / 64, 1), 256>>>(x, sg, su, 1);
    gemm2_kernel<<<dim3(H / 64, T / 64, 1), 256>>>(sd, out, 1);

    // routed experts (sparse, grouped by expert; early-exit beyond count)
    gemm1_kernel<<<dim3(I / 64, T / 64, E), 256>>>(x, gw, uw, 0);
    gemm2_kernel<<<dim3(H / 64, T / 64, E), 256>>>(dw, out, 0);

    finalize_kernel<<<1, 256>>>(out);
}

// round 3
// speedup vs baseline: 3.1164x; 3.1164x over previous
#include <cuda_runtime.h>
#include <cuda_bf16.h>
#include <cstdint>
#include <math.h>

#define H 1024
#define I 2048
#define E 8
#define T 4096

// out layout: [0, T*H) routed ; [T*H] aux ; [T*H+1] z ; [T*H+2, +T*E) logits
#define OUT_AUX   (T*H)
#define OUT_Z     (T*H + 1)
#define OUT_LOG   (T*H + 2)

// GEMM tiling
#define BM 128
#define BN 64
#define BK 16
#define APAD 4      // A smem row stride 20 -> conflict-free fragment reads
#define BPAD 8      // B smem row stride 72 -> conflict-free fragment reads

// ---------------- device scratch (allocation-free contract) ----------------
__device__ int   g_count[E];
__device__ int   g_tok[E][T];
__device__ float g_wt[E][T];
__device__ float g_probs[T * E];
__device__ float g_z[T];
__device__ float g_inter[(size_t)E * T * I];       // expert SwiGLU intermediate
__device__ float g_shared_inter[(size_t)T * I];    // shared-expert intermediate

__device__ __forceinline__ float silu(float v) { return v / (1.0f + expf(-v)); }

__device__ __forceinline__ uint32_t smem_u32(const void* p) {
    return (uint32_t)__cvta_generic_to_shared(p);
}
__device__ __forceinline__ void cp16(uint32_t dst, const void* src, bool pred) {
    int sz = pred ? 16 : 0;
    asm volatile("cp.async.cg.shared.global [%0], [%1], 16, %2;\n"
                 :: "r"(dst), "l"(src), "r"(sz));
}
__device__ __forceinline__ void cp_commit() { asm volatile("cp.async.commit_group;\n"); }
__device__ __forceinline__ void cp_wait1()  { asm volatile("cp.async.wait_group 1;\n"); }

__device__ __forceinline__ uint32_t f2tf32(float f) {
    uint32_t r; asm("cvt.rna.tf32.f32 %0, %1;\n" : "=r"(r) : "f"(f)); return r;
}
__device__ __forceinline__ void mma_tf32(float* c, const uint32_t* a, const uint32_t* b) {
    asm volatile("mma.sync.aligned.m16n8k8.row.col.f32.tf32.tf32.f32 "
                 "{%0,%1,%2,%3}, {%4,%5,%6,%7}, {%8,%9}, {%0,%1,%2,%3};\n"
                 : "+f"(c[0]), "+f"(c[1]), "+f"(c[2]), "+f"(c[3])
                 : "r"(a[0]), "r"(a[1]), "r"(a[2]), "r"(a[3]),
                   "r"(b[0]), "r"(b[1]));
}

// ---------------- init ----------------
__global__ void init_kernel() {
    int i = threadIdx.x;
    if (i < E) g_count[i] = 0;
}

// ---------------- router: logits, softmax, top-2, lists, loss partials ----
__global__ void router_kernel(const float* __restrict__ x,
                              const float* __restrict__ rw,
                              float* __restrict__ out_logits) {
    int t = blockIdx.x;
    int tid = threadIdx.x;                 // 256 threads
    const float* xr = x + (size_t)t * H;

    float p[E];
#pragma unroll
    for (int e = 0; e < E; e++) p[e] = 0.0f;

    for (int h = tid; h < H; h += 256) {
        float xv = xr[h];
        const float* r = rw + (size_t)h * E;
#pragma unroll
        for (int e = 0; e < E; e++) p[e] += xv * r[e];
    }

#pragma unroll
    for (int off = 16; off > 0; off >>= 1) {
#pragma unroll
        for (int e = 0; e < E; e++)
            p[e] += __shfl_down_sync(0xFFFFFFFFu, p[e], off);
    }

    __shared__ float sred[8][E];
    int warp = tid >> 5, lane = tid & 31;
    if (lane == 0) {
#pragma unroll
        for (int e = 0; e < E; e++) sred[warp][e] = p[e];
    }
    __syncthreads();

    if (tid == 0) {
        float logit[E];
#pragma unroll
        for (int e = 0; e < E; e++) {
            float s = 0.0f;
#pragma unroll
            for (int w = 0; w < 8; w++) s += sred[w][e];
            logit[e] = s;
            out_logits[(size_t)t * E + e] = s;
        }
        float mx = logit[0];
#pragma unroll
        for (int e = 1; e < E; e++) mx = fmaxf(mx, logit[e]);
        float se = 0.0f, pr[E];
#pragma unroll
        for (int e = 0; e < E; e++) { pr[e] = expf(logit[e] - mx); se += pr[e]; }
        float inv = 1.0f / se;
#pragma unroll
        for (int e = 0; e < E; e++) {
            pr[e] *= inv;
            g_probs[(size_t)t * E + e] = pr[e];
        }
        float lse = mx + logf(se);
        g_z[t] = lse * lse;

        int i0 = 0;
#pragma unroll
        for (int e = 1; e < E; e++) if (pr[e] > pr[i0]) i0 = e;
        int i1 = (i0 == 0) ? 1 : 0;
#pragma unroll
        for (int e = 0; e < E; e++)
            if (e != i0 && pr[e] > pr[i1]) i1 = e;

        float w0 = pr[i0], w1 = pr[i1];
        float ws = 1.0f / (w0 + w1);
        w0 *= ws; w1 *= ws;

        int s0 = atomicAdd(&g_count[i0], 1);
        g_tok[i0][s0] = t; g_wt[i0][s0] = w0;
        int s1 = atomicAdd(&g_count[i1], 1);
        g_tok[i1][s1] = t; g_wt[i1][s1] = w1;
    }
}

// ---------------- GEMM1 (tf32 mma): inter = silu(X@G) * (X@U) ----------------
__global__ void __launch_bounds__(256, 2)
gemm1_kernel(const float* __restrict__ x,
             const float* __restrict__ gw,
             const float* __restrict__ uw,
             int shared_mode) {
    int e   = shared_mode ? 0 : blockIdx.z;
    int cnt = shared_mode ? T : g_count[e];
    int m0  = blockIdx.y * BM;
    if (m0 >= cnt) return;
    int n0 = blockIdx.x * BN;

    size_t woff = shared_mode ? 0 : (size_t)e * H * I;
    float* inter = shared_mode ? g_shared_inter : (g_inter + (size_t)e * T * I);

    __shared__ float As[2][BM][BK + APAD];
    __shared__ float Bg[2][BK][BN + BPAD];
    __shared__ float Bu[2][BK][BN + BPAD];

    int u = threadIdx.x;
    int lane = u & 31, warp = u >> 5;
    int wm = warp & 3, wn = warp >> 2;
    int r = lane >> 2, c = lane & 3;

    // A copy assignments (2 float4 per thread), fixed rows across k-iters
    int am[2], akq[2]; const float* aptr[2]; bool aval[2];
#pragma unroll
    for (int j = 0; j < 2; j++) {
        int idx = j * 256 + u;
        am[j]  = idx >> 2;
        akq[j] = idx & 3;
        bool v = (m0 + am[j]) < cnt;
        int token = shared_mode ? (m0 + am[j]) : (v ? g_tok[e][m0 + am[j]] : 0);
        aptr[j] = x + (size_t)token * H + akq[j] * 4;
        aval[j] = v;
    }
    // B copy assignment (1 float4 per thread per matrix)
    int bk = u >> 4, bnq = u & 15;
    const float* gptr = gw + woff + (size_t)bk * I + n0 + bnq * 4;
    const float* uptr = uw + woff + (size_t)bk * I + n0 + bnq * 4;

    float accG[2][4][4] = {}, accU[2][4][4] = {};

    // prologue
    {
#pragma unroll
        for (int j = 0; j < 2; j++)
            cp16(smem_u32(&As[0][am[j]][akq[j] * 4]), aptr[j], aval[j]);
        cp16(smem_u32(&Bg[0][bk][bnq * 4]), gptr, true);
        cp16(smem_u32(&Bu[0][bk][bnq * 4]), uptr, true);
        cp_commit();
    }

    const int NIT = H / BK;
    for (int it = 0; it < NIT; ++it) {
        if (it + 1 < NIT) {
            int k0 = (it + 1) * BK;
            int s  = (it + 1) & 1;
#pragma unroll
            for (int j = 0; j < 2; j++)
                cp16(smem_u32(&As[s][am[j]][akq[j] * 4]), aptr[j] + k0, aval[j]);
            cp16(smem_u32(&Bg[s][bk][bnq * 4]), gptr + (size_t)k0 * I, true);
            cp16(smem_u32(&Bu[s][bk][bnq * 4]), uptr + (size_t)k0 * I, true);
        }
        cp_commit();
        cp_wait1();
        __syncthreads();
        int s = it & 1;
#pragma unroll
        for (int ks = 0; ks < 2; ks++) {
            uint32_t a[2][4];
#pragma unroll
            for (int mt = 0; mt < 2; mt++) {
                int mr = wm * 32 + mt * 16;
                a[mt][0] = f2tf32(As[s][mr + r    ][ks * 8 + c    ]);
                a[mt][1] = f2tf32(As[s][mr + r + 8][ks * 8 + c    ]);
                a[mt][2] = f2tf32(As[s][mr + r    ][ks * 8 + c + 4]);
                a[mt][3] = f2tf32(As[s][mr + r + 8][ks * 8 + c + 4]);
            }
#pragma unroll
            for (int nt = 0; nt < 4; nt++) {
                int nc = wn * 32 + nt * 8 + r;
                uint32_t bgf[2], buf[2];
                bgf[0] = f2tf32(Bg[s][ks * 8 + c    ][nc]);
                bgf[1] = f2tf32(Bg[s][ks * 8 + c + 4][nc]);
                buf[0] = f2tf32(Bu[s][ks * 8 + c    ][nc]);
                buf[1] = f2tf32(Bu[s][ks * 8 + c + 4][nc]);
#pragma unroll
                for (int mt = 0; mt < 2; mt++) {
                    mma_tf32(accG[mt][nt], a[mt], bgf);
                    mma_tf32(accU[mt][nt], a[mt], buf);
                }
            }
        }
        __syncthreads();
    }

    // epilogue: silu(gate) * up -> inter
#pragma unroll
    for (int mt = 0; mt < 2; mt++) {
#pragma unroll
        for (int hrow = 0; hrow < 2; hrow++) {
            int rr = m0 + wm * 32 + mt * 16 + r + hrow * 8;
            if (rr >= cnt) continue;
#pragma unroll
            for (int nt = 0; nt < 4; nt++) {
                int col = n0 + wn * 32 + nt * 8 + 2 * c;
                float g0 = accG[mt][nt][hrow * 2 + 0];
                float g1 = accG[mt][nt][hrow * 2 + 1];
                float u0 = accU[mt][nt][hrow * 2 + 0];
                float u1 = accU[mt][nt][hrow * 2 + 1];
                float2 o = make_float2(silu(g0) * u0, silu(g1) * u1);
                *reinterpret_cast<float2*>(inter + (size_t)rr * I + col) = o;
            }
        }
    }
}

// ---------------- GEMM2 (tf32 mma): routed (+)= w * (inter @ D) ----------------
__global__ void __launch_bounds__(256, 2)
gemm2_kernel(const float* __restrict__ dw,
             float* __restrict__ routed,
             int shared_mode) {
    int e   = shared_mode ? 0 : blockIdx.z;
    int cnt = shared_mode ? T : g_count[e];
    int m0  = blockIdx.y * BM;
    if (m0 >= cnt) return;
    int n0 = blockIdx.x * BN;

    size_t woff = shared_mode ? 0 : (size_t)e * I * H;
    const float* inter = shared_mode ? g_shared_inter : (g_inter + (size_t)e * T * I);

    __shared__ float As[2][BM][BK + APAD];
    __shared__ float Bd[2][BK][BN + BPAD];

    int u = threadIdx.x;
    int lane = u & 31, warp = u >> 5;
    int wm = warp & 3, wn = warp >> 2;
    int r = lane >> 2, c = lane & 3;

    int am[2], akq[2]; const float* aptr[2]; bool aval[2];
#pragma unroll
    for (int j = 0; j < 2; j++) {
        int idx = j * 256 + u;
        am[j]  = idx >> 2;
        akq[j] = idx & 3;
        bool v = (m0 + am[j]) < cnt;
        aptr[j] = inter + (size_t)(v ? (m0 + am[j]) : 0) * I + akq[j] * 4;
        aval[j] = v;
    }
    int bk = u >> 4, bnq = u & 15;
    const float* dptr = dw + woff + (size_t)bk * H + n0 + bnq * 4;

    float acc[2][4][4] = {};

    {
#pragma unroll
        for (int j = 0; j < 2; j++)
            cp16(smem_u32(&As[0][am[j]][akq[j] * 4]), aptr[j], aval[j]);
        cp16(smem_u32(&Bd[0][bk][bnq * 4]), dptr, true);
        cp_commit();
    }

    const int NIT = I / BK;
    for (int it = 0; it < NIT; ++it) {
        if (it + 1 < NIT) {
            int k0 = (it + 1) * BK;
            int s  = (it + 1) & 1;
#pragma unroll
            for (int j = 0; j < 2; j++)
                cp16(smem_u32(&As[s][am[j]][akq[j] * 4]), aptr[j] + k0, aval[j]);
            cp16(smem_u32(&Bd[s][bk][bnq * 4]), dptr + (size_t)k0 * H, true);
        }
        cp_commit();
        cp_wait1();
        __syncthreads();
        int s = it & 1;
#pragma unroll
        for (int ks = 0; ks < 2; ks++) {
            uint32_t a[2][4];
#pragma unroll
            for (int mt = 0; mt < 2; mt++) {
                int mr = wm * 32 + mt * 16;
                a[mt][0] = f2tf32(As[s][mr + r    ][ks * 8 + c    ]);
                a[mt][1] = f2tf32(As[s][mr + r + 8][ks * 8 + c    ]);
                a[mt][2] = f2tf32(As[s][mr + r    ][ks * 8 + c + 4]);
                a[mt][3] = f2tf32(As[s][mr + r + 8][ks * 8 + c + 4]);
            }
#pragma unroll
            for (int nt = 0; nt < 4; nt++) {
                int nc = wn * 32 + nt * 8 + r;
                uint32_t bb[2];
                bb[0] = f2tf32(Bd[s][ks * 8 + c    ][nc]);
                bb[1] = f2tf32(Bd[s][ks * 8 + c + 4][nc]);
#pragma unroll
                for (int mt = 0; mt < 2; mt++)
                    mma_tf32(acc[mt][nt], a[mt], bb);
            }
        }
        __syncthreads();
    }

#pragma unroll
    for (int mt = 0; mt < 2; mt++) {
#pragma unroll
        for (int hrow = 0; hrow < 2; hrow++) {
            int rr = m0 + wm * 32 + mt * 16 + r + hrow * 8;
            if (rr >= cnt) continue;
            if (shared_mode) {
#pragma unroll
                for (int nt = 0; nt < 4; nt++) {
                    int col = n0 + wn * 32 + nt * 8 + 2 * c;
                    float2 o = make_float2(acc[mt][nt][hrow * 2 + 0],
                                           acc[mt][nt][hrow * 2 + 1]);
                    *reinterpret_cast<float2*>(routed + (size_t)rr * H + col) = o;
                }
            } else {
                int token = g_tok[e][rr];
                float w = g_wt[e][rr];
                float* dst = routed + (size_t)token * H;
#pragma unroll
                for (int nt = 0; nt < 4; nt++) {
                    int col = n0 + wn * 32 + nt * 8 + 2 * c;
                    atomicAdd(dst + col + 0, w * acc[mt][nt][hrow * 2 + 0]);
                    atomicAdd(dst + col + 1, w * acc[mt][nt][hrow * 2 + 1]);
                }
            }
        }
    }
}

// ---------------- finalize losses ----------------
__global__ void finalize_kernel(float* __restrict__ out) {
    int tid = threadIdx.x;   // 256
    float ps[E];
#pragma unroll
    for (int e = 0; e < E; e++) ps[e] = 0.0f;
    float zs = 0.0f;
    for (int t = tid; t < T; t += 256) {
        zs += g_z[t];
#pragma unroll
        for (int e = 0; e < E; e++) ps[e] += g_probs[(size_t)t * E + e];
    }
#pragma unroll
    for (int off = 16; off > 0; off >>= 1) {
        zs += __shfl_down_sync(0xFFFFFFFFu, zs, off);
#pragma unroll
        for (int e = 0; e < E; e++)
            ps[e] += __shfl_down_sync(0xFFFFFFFFu, ps[e], off);
    }
    __shared__ float sp[8][E];
    __shared__ float sz[8];
    int warp = tid >> 5, lane = tid & 31;
    if (lane == 0) {
        sz[warp] = zs;
#pragma unroll
        for (int e = 0; e < E; e++) sp[warp][e] = ps[e];
    }
    __syncthreads();
    if (tid == 0) {
        float ztot = 0.0f;
        float ptot[E];
#pragma unroll
        for (int e = 0; e < E; e++) ptot[e] = 0.0f;
#pragma unroll
        for (int w = 0; w < 8; w++) {
            ztot += sz[w];
#pragma unroll
            for (int e = 0; e < E; e++) ptot[e] += sp[w][e];
        }
        float aux = 0.0f;
#pragma unroll
        for (int e = 0; e < E; e++) {
            float tpe = 0.5f * (float)g_count[e] / (float)T;
            float ppe = ptot[e] / (float)T;
            aux += tpe * ppe;
        }
        out[OUT_AUX] = (float)E * aux;
        out[OUT_Z]   = ztot / (float)T;
    }
}

// ---------------- launch ----------------
extern "C" void kernel_launch(void* const* d_in, const int* in_sizes, int n_in,
                              void* d_out, int out_size) {
    const float* x  = (const float*)d_in[0];
    const float* rw = (const float*)d_in[1];
    const float* gw = (const float*)d_in[2];
    const float* uw = (const float*)d_in[3];
    const float* dw = (const float*)d_in[4];
    const float* sg = (const float*)d_in[5];
    const float* su = (const float*)d_in[6];
    const float* sd = (const float*)d_in[7];
    float* out = (float*)d_out;

    init_kernel<<<1, 32>>>();
    router_kernel<<<T, 256>>>(x, rw, out + OUT_LOG);

    // shared expert (dense); its GEMM2 plain-writes routed
    gemm1_kernel<<<dim3(I / BN, T / BM, 1), 256>>>(x, sg, su, 1);
    gemm2_kernel<<<dim3(H / BN, T / BM, 1), 256>>>(sd, out, 1);

    // routed experts (sparse, grouped by expert; early-exit beyond count)
    gemm1_kernel<<<dim3(I / BN, T / BM, E), 256>>>(x, gw, uw, 0);
    gemm2_kernel<<<dim3(H / BN, T / BM, E), 256>>>(dw, out, 0);

    finalize_kernel<<<1, 256>>>(out);
}

// round 5
// speedup vs baseline: 3.4636x; 1.1114x over previous
#include <cuda_runtime.h>
#include <cuda_bf16.h>
#include <cstdint>
#include <math.h>

#define H 1024
#define I 2048
#define E 8
#define T 4096

// out layout: [0, T*H) routed ; [T*H] aux ; [T*H+1] z ; [T*H+2, +T*E) logits
#define OUT_AUX   (T*H)
#define OUT_Z     (T*H + 1)
#define OUT_LOG   (T*H + 2)

// GEMM tiling
#define BM 128
#define BN 64
#define BK 32
#define ASTR 36     // A smem row stride (floats): conflict-free fragment reads
#define BSTR 72     // B smem row stride

// ---------------- device scratch (allocation-free contract) ----------------
__device__ int   g_count[E];
__device__ int   g_tok[E][T];
__device__ float g_wt[E][T];
__device__ float g_probs[T * E];
__device__ float g_z[T];
__device__ float g_inter[(size_t)E * T * I];     // tf32-rounded SwiGLU intermediate
__device__ float g_xr [(size_t)T * H];           // tf32-rounded x
__device__ float g_gwr[(size_t)E * H * I];       // tf32-rounded weights
__device__ float g_uwr[(size_t)E * H * I];
__device__ float g_dwr[(size_t)E * I * H];
__device__ float g_sgr[(size_t)H * I];
__device__ float g_sur[(size_t)H * I];
__device__ float g_sdr[(size_t)I * H];

__device__ __forceinline__ float silu(float v) { return v / (1.0f + expf(-v)); }

__device__ __forceinline__ uint32_t tf32bits(float f) {
    uint32_t r; asm("cvt.rna.tf32.f32 %0, %1;\n" : "=r"(r) : "f"(f)); return r;
}
__device__ __forceinline__ uint32_t smem_u32(const void* p) {
    return (uint32_t)__cvta_generic_to_shared(p);
}
__device__ __forceinline__ void cp16(uint32_t dst, const void* src, bool pred) {
    int sz = pred ? 16 : 0;
    asm volatile("cp.async.cg.shared.global [%0], [%1], 16, %2;\n"
                 :: "r"(dst), "l"(src), "r"(sz));
}
__device__ __forceinline__ void cp_commit() { asm volatile("cp.async.commit_group;\n"); }
__device__ __forceinline__ void cp_wait1()  { asm volatile("cp.async.wait_group 1;\n"); }

__device__ __forceinline__ void mma_tf32(float* c, const uint32_t* a, const uint32_t* b) {
    asm volatile("mma.sync.aligned.m16n8k8.row.col.f32.tf32.tf32.f32 "
                 "{%0,%1,%2,%3}, {%4,%5,%6,%7}, {%8,%9}, {%0,%1,%2,%3};\n"
                 : "+f"(c[0]), "+f"(c[1]), "+f"(c[2]), "+f"(c[3])
                 : "r"(a[0]), "r"(a[1]), "r"(a[2]), "r"(a[3]),
                   "r"(b[0]), "r"(b[1]));
}

// ---------------- prep: tf32 rounding ----------------
__global__ void round_kernel(const float* __restrict__ src, float* __restrict__ dst, int n4) {
    int i = blockIdx.x * blockDim.x + threadIdx.x;
    if (i >= n4) return;
    float4 v = reinterpret_cast<const float4*>(src)[i];
    v.x = __uint_as_float(tf32bits(v.x));
    v.y = __uint_as_float(tf32bits(v.y));
    v.z = __uint_as_float(tf32bits(v.z));
    v.w = __uint_as_float(tf32bits(v.w));
    reinterpret_cast<float4*>(dst)[i] = v;
}

__global__ void zero_routed(float* __restrict__ out) {
    int i = blockIdx.x * blockDim.x + threadIdx.x;
    float4 z = make_float4(0.f, 0.f, 0.f, 0.f);
    reinterpret_cast<float4*>(out)[i] = z;     // grid covers T*H/4
}

// ---------------- init ----------------
__global__ void init_kernel() {
    int i = threadIdx.x;
    if (i < E) g_count[i] = 0;
}

// ---------------- router ----------------
__global__ void router_kernel(const float* __restrict__ x,
                              const float* __restrict__ rw,
                              float* __restrict__ out_logits) {
    int t = blockIdx.x;
    int tid = threadIdx.x;
    const float* xr = x + (size_t)t * H;

    float p[E];
#pragma unroll
    for (int e = 0; e < E; e++) p[e] = 0.0f;
    for (int h = tid; h < H; h += 256) {
        float xv = xr[h];
        const float* r = rw + (size_t)h * E;
#pragma unroll
        for (int e = 0; e < E; e++) p[e] += xv * r[e];
    }
#pragma unroll
    for (int off = 16; off > 0; off >>= 1)
#pragma unroll
        for (int e = 0; e < E; e++)
            p[e] += __shfl_down_sync(0xFFFFFFFFu, p[e], off);

    __shared__ float sred[8][E];
    int warp = tid >> 5, lane = tid & 31;
    if (lane == 0)
#pragma unroll
        for (int e = 0; e < E; e++) sred[warp][e] = p[e];
    __syncthreads();

    if (tid == 0) {
        float logit[E];
#pragma unroll
        for (int e = 0; e < E; e++) {
            float s = 0.0f;
#pragma unroll
            for (int w = 0; w < 8; w++) s += sred[w][e];
            logit[e] = s;
            out_logits[(size_t)t * E + e] = s;
        }
        float mx = logit[0];
#pragma unroll
        for (int e = 1; e < E; e++) mx = fmaxf(mx, logit[e]);
        float se = 0.0f, pr[E];
#pragma unroll
        for (int e = 0; e < E; e++) { pr[e] = expf(logit[e] - mx); se += pr[e]; }
        float inv = 1.0f / se;
#pragma unroll
        for (int e = 0; e < E; e++) { pr[e] *= inv; g_probs[(size_t)t * E + e] = pr[e]; }
        float lse = mx + logf(se);
        g_z[t] = lse * lse;

        int i0 = 0;
#pragma unroll
        for (int e = 1; e < E; e++) if (pr[e] > pr[i0]) i0 = e;
        int i1 = (i0 == 0) ? 1 : 0;
#pragma unroll
        for (int e = 0; e < E; e++) if (e != i0 && pr[e] > pr[i1]) i1 = e;

        float w0 = pr[i0], w1 = pr[i1];
        float ws = 1.0f / (w0 + w1);
        w0 *= ws; w1 *= ws;
        int s0 = atomicAdd(&g_count[i0], 1);
        g_tok[i0][s0] = t; g_wt[i0][s0] = w0;
        int s1 = atomicAdd(&g_count[i1], 1);
        g_tok[i1][s1] = t; g_wt[i1][s1] = w1;
    }
}

// ---------------- GEMM1: inter = tf32(silu(X@G) * (X@U)) ----------------
// grid (I/64, T/128, E+1); z==E -> shared expert
__global__ void __launch_bounds__(256, 2)
gemm1_kernel() {
    extern __shared__ float sm[];
    float* As = sm;                                  // 2 * BM * ASTR
    float* Bg = As + 2 * BM * ASTR;                  // 2 * BK * BSTR
    float* Bu = Bg + 2 * BK * BSTR;

    int z = blockIdx.z;
    bool shm = (z == E);
    int e   = shm ? 0 : z;
    int cnt = shm ? T : g_count[e];
    int m0  = blockIdx.y * BM;
    if (m0 >= cnt) return;
    int n0 = blockIdx.x * BN;

    const float* gsrc = shm ? g_sgr : (g_gwr + (size_t)e * H * I);
    const float* usrc = shm ? g_sur : (g_uwr + (size_t)e * H * I);
    float* inter = g_inter + (size_t)(shm ? 0 : e) * T * I;
    // shared expert reuses expert-0 slice? NO -- overlap. Use dedicated region:
    // place shared at e index via separate pointer below.
    if (shm) inter = g_inter;            // careful: give shared its own space
    // To avoid overlap with expert 0, shared uses the tail of g_xr? Not enough.
    // Instead: shared uses g_inter offset by expert slot E? Buffer is E*T*I.
    // Solution: experts use slots 0..E-1 only when z<E; shared gets no slot.
    // => allocate shared inter in g_inter is WRONG. Use g_sir below.

    int tid = threadIdx.x;
    int lane = tid & 31, warp = tid >> 5;
    int wm = warp & 3, wn = warp >> 2;
    int r = lane >> 2, c = lane & 3;

    // A loads: 4x 16B chunks/thread; rows fixed across k-iters
    const float* asrc[4]; bool aval[4]; uint32_t aoff[4];
#pragma unroll
    for (int j = 0; j < 4; j++) {
        int item = tid + j * 256;
        int arow = item >> 3, achk = item & 7;
        int rr = m0 + arow;
        bool v = rr < cnt;
        int token = shm ? rr : (v ? g_tok[e][rr] : 0);
        asrc[j] = g_xr + (size_t)token * H + achk * 4;
        aval[j] = v;
        aoff[j] = (uint32_t)(arow * ASTR + achk * 4);
    }
    // B loads: 2x 16B chunks/thread per matrix
    const float* gptr[2]; const float* uptr[2]; uint32_t boff[2];
#pragma unroll
    for (int j = 0; j < 2; j++) {
        int item = tid + j * 256;
        int brow = item >> 4, bchk = item & 15;
        gptr[j] = gsrc + (size_t)brow * I + n0 + bchk * 4;
        uptr[j] = usrc + (size_t)brow * I + n0 + bchk * 4;
        boff[j] = (uint32_t)(brow * BSTR + bchk * 4);
    }

    float accG[2][4][4] = {}, accU[2][4][4] = {};

    // prologue: stage 0
#pragma unroll
    for (int j = 0; j < 4; j++) cp16(smem_u32(As + aoff[j]), asrc[j], aval[j]);
#pragma unroll
    for (int j = 0; j < 2; j++) {
        cp16(smem_u32(Bg + boff[j]), gptr[j], true);
        cp16(smem_u32(Bu + boff[j]), uptr[j], true);
    }
    cp_commit();

    const int NIT = H / BK;   // 32
    for (int it = 0; it < NIT; ++it) {
        if (it + 1 < NIT) {
            int k0 = (it + 1) * BK;
            int so = ((it + 1) & 1) ? BM * ASTR : 0;
            int sb = ((it + 1) & 1) ? BK * BSTR : 0;
#pragma unroll
            for (int j = 0; j < 4; j++)
                cp16(smem_u32(As + so + aoff[j]), asrc[j] + k0, aval[j]);
#pragma unroll
            for (int j = 0; j < 2; j++) {
                cp16(smem_u32(Bg + sb + boff[j]), gptr[j] + (size_t)k0 * I, true);
                cp16(smem_u32(Bu + sb + boff[j]), uptr[j] + (size_t)k0 * I, true);
            }
        }
        cp_commit();
        cp_wait1();
        __syncthreads();
        const float* Asl = As + ((it & 1) ? BM * ASTR : 0);
        const float* Bgl = Bg + ((it & 1) ? BK * BSTR : 0);
        const float* Bul = Bu + ((it & 1) ? BK * BSTR : 0);
#pragma unroll
        for (int ks = 0; ks < 4; ks++) {
            uint32_t a[2][4];
#pragma unroll
            for (int mt = 0; mt < 2; mt++) {
                int mr = wm * 32 + mt * 16;
                a[mt][0] = __float_as_uint(Asl[(mr + r    ) * ASTR + ks * 8 + c    ]);
                a[mt][1] = __float_as_uint(Asl[(mr + r + 8) * ASTR + ks * 8 + c    ]);
                a[mt][2] = __float_as_uint(Asl[(mr + r    ) * ASTR + ks * 8 + c + 4]);
                a[mt][3] = __float_as_uint(Asl[(mr + r + 8) * ASTR + ks * 8 + c + 4]);
            }
#pragma unroll
            for (int nt = 0; nt < 4; nt++) {
                int nc = wn * 32 + nt * 8 + r;
                uint32_t bg[2], bu[2];
                bg[0] = __float_as_uint(Bgl[(ks * 8 + c    ) * BSTR + nc]);
                bg[1] = __float_as_uint(Bgl[(ks * 8 + c + 4) * BSTR + nc]);
                bu[0] = __float_as_uint(Bul[(ks * 8 + c    ) * BSTR + nc]);
                bu[1] = __float_as_uint(Bul[(ks * 8 + c + 4) * BSTR + nc]);
#pragma unroll
                for (int mt = 0; mt < 2; mt++) {
                    mma_tf32(accG[mt][nt], a[mt], bg);
                    mma_tf32(accU[mt][nt], a[mt], bu);
                }
            }
        }
        __syncthreads();
    }

    // epilogue: tf32-rounded silu(g)*u
    float* ibase = shm ? (g_inter + (size_t)E * 0)      // placeholder, fixed below
                       : (g_inter + (size_t)e * T * I);
    // shared expert writes into its own dedicated buffer:
    //   we reuse g_dwr? no. Use a real dedicated global:
    // (declared below main scratch) -- see g_sinter
    extern __device__ float g_sinter[];
    if (shm) ibase = g_sinter;

#pragma unroll
    for (int mt = 0; mt < 2; mt++) {
#pragma unroll
        for (int hrow = 0; hrow < 2; hrow++) {
            int rr = m0 + wm * 32 + mt * 16 + r + hrow * 8;
            if (rr >= cnt) continue;
#pragma unroll
            for (int nt = 0; nt < 4; nt++) {
                int col = n0 + wn * 32 + nt * 8 + 2 * c;
                float g0 = accG[mt][nt][hrow * 2 + 0];
                float g1 = accG[mt][nt][hrow * 2 + 1];
                float u0 = accU[mt][nt][hrow * 2 + 0];
                float u1 = accU[mt][nt][hrow * 2 + 1];
                float2 o;
                o.x = __uint_as_float(tf32bits(silu(g0) * u0));
                o.y = __uint_as_float(tf32bits(silu(g1) * u1));
                *reinterpret_cast<float2*>(ibase + (size_t)rr * I + col) = o;
            }
        }
    }
}

__device__ float g_sinter[(size_t)T * I];     // shared-expert intermediate

// ---------------- GEMM2: routed += w * (inter @ D) (atomic everywhere) ----
// grid (H/64, T/128, E+1); z==E -> shared expert (w = 1)
__global__ void __launch_bounds__(256, 2)
gemm2_kernel(float* __restrict__ routed) {
    extern __shared__ float sm[];
    float* As = sm;
    float* Bd = As + 2 * BM * ASTR;

    int z = blockIdx.z;
    bool shm = (z == E);
    int e   = shm ? 0 : z;
    int cnt = shm ? T : g_count[e];
    int m0  = blockIdx.y * BM;
    if (m0 >= cnt) return;
    int n0 = blockIdx.x * BN;

    const float* dsrc = shm ? g_sdr : (g_dwr + (size_t)e * I * H);
    const float* inter = shm ? g_sinter : (g_inter + (size_t)e * T * I);

    int tid = threadIdx.x;
    int lane = tid & 31, warp = tid >> 5;
    int wm = warp & 3, wn = warp >> 2;
    int r = lane >> 2, c = lane & 3;

    const float* asrc[4]; bool aval[4]; uint32_t aoff[4];
#pragma unroll
    for (int j = 0; j < 4; j++) {
        int item = tid + j * 256;
        int arow = item >> 3, achk = item & 7;
        int rr = m0 + arow;
        bool v = rr < cnt;
        asrc[j] = inter + (size_t)(v ? rr : 0) * I + achk * 4;
        aval[j] = v;
        aoff[j] = (uint32_t)(arow * ASTR + achk * 4);
    }
    const float* dptr[2]; uint32_t boff[2];
#pragma unroll
    for (int j = 0; j < 2; j++) {
        int item = tid + j * 256;
        int brow = item >> 4, bchk = item & 15;
        dptr[j] = dsrc + (size_t)brow * H + n0 + bchk * 4;
        boff[j] = (uint32_t)(brow * BSTR + bchk * 4);
    }

    float acc[2][4][4] = {};

#pragma unroll
    for (int j = 0; j < 4; j++) cp16(smem_u32(As + aoff[j]), asrc[j], aval[j]);
#pragma unroll
    for (int j = 0; j < 2; j++) cp16(smem_u32(Bd + boff[j]), dptr[j], true);
    cp_commit();

    const int NIT = I / BK;   // 64
    for (int it = 0; it < NIT; ++it) {
        if (it + 1 < NIT) {
            int k0 = (it + 1) * BK;
            int so = ((it + 1) & 1) ? BM * ASTR : 0;
            int sb = ((it + 1) & 1) ? BK * BSTR : 0;
#pragma unroll
            for (int j = 0; j < 4; j++)
                cp16(smem_u32(As + so + aoff[j]), asrc[j] + k0, aval[j]);
#pragma unroll
            for (int j = 0; j < 2; j++)
                cp16(smem_u32(Bd + sb + boff[j]), dptr[j] + (size_t)k0 * H, true);
        }
        cp_commit();
        cp_wait1();
        __syncthreads();
        const float* Asl = As + ((it & 1) ? BM * ASTR : 0);
        const float* Bdl = Bd + ((it & 1) ? BK * BSTR : 0);
#pragma unroll
        for (int ks = 0; ks < 4; ks++) {
            uint32_t a[2][4];
#pragma unroll
            for (int mt = 0; mt < 2; mt++) {
                int mr = wm * 32 + mt * 16;
                a[mt][0] = __float_as_uint(Asl[(mr + r    ) * ASTR + ks * 8 + c    ]);
                a[mt][1] = __float_as_uint(Asl[(mr + r + 8) * ASTR + ks * 8 + c    ]);
                a[mt][2] = __float_as_uint(Asl[(mr + r    ) * ASTR + ks * 8 + c + 4]);
                a[mt][3] = __float_as_uint(Asl[(mr + r + 8) * ASTR + ks * 8 + c + 4]);
            }
#pragma unroll
            for (int nt = 0; nt < 4; nt++) {
                int nc = wn * 32 + nt * 8 + r;
                uint32_t bb[2];
                bb[0] = __float_as_uint(Bdl[(ks * 8 + c    ) * BSTR + nc]);
                bb[1] = __float_as_uint(Bdl[(ks * 8 + c + 4) * BSTR + nc]);
#pragma unroll
                for (int mt = 0; mt < 2; mt++)
                    mma_tf32(acc[mt][nt], a[mt], bb);
            }
        }
        __syncthreads();
    }

#pragma unroll
    for (int mt = 0; mt < 2; mt++) {
#pragma unroll
        for (int hrow = 0; hrow < 2; hrow++) {
            int rr = m0 + wm * 32 + mt * 16 + r + hrow * 8;
            if (rr >= cnt) continue;
            int token = shm ? rr : g_tok[e][rr];
            float w = shm ? 1.0f : g_wt[e][rr];
            float* dst = routed + (size_t)token * H;
#pragma unroll
            for (int nt = 0; nt < 4; nt++) {
                int col = n0 + wn * 32 + nt * 8 + 2 * c;
                atomicAdd(dst + col + 0, w * acc[mt][nt][hrow * 2 + 0]);
                atomicAdd(dst + col + 1, w * acc[mt][nt][hrow * 2 + 1]);
            }
        }
    }
}

// ---------------- finalize losses ----------------
__global__ void finalize_kernel(float* __restrict__ out) {
    int tid = threadIdx.x;
    float ps[E];
#pragma unroll
    for (int e = 0; e < E; e++) ps[e] = 0.0f;
    float zs = 0.0f;
    for (int t = tid; t < T; t += 256) {
        zs += g_z[t];
#pragma unroll
        for (int e = 0; e < E; e++) ps[e] += g_probs[(size_t)t * E + e];
    }
#pragma unroll
    for (int off = 16; off > 0; off >>= 1) {
        zs += __shfl_down_sync(0xFFFFFFFFu, zs, off);
#pragma unroll
        for (int e = 0; e < E; e++)
            ps[e] += __shfl_down_sync(0xFFFFFFFFu, ps[e], off);
    }
    __shared__ float sp[8][E];
    __shared__ float sz[8];
    int warp = tid >> 5, lane = tid & 31;
    if (lane == 0) {
        sz[warp] = zs;
#pragma unroll
        for (int e = 0; e < E; e++) sp[warp][e] = ps[e];
    }
    __syncthreads();
    if (tid == 0) {
        float ztot = 0.0f, ptot[E];
#pragma unroll
        for (int e = 0; e < E; e++) ptot[e] = 0.0f;
#pragma unroll
        for (int w = 0; w < 8; w++) {
            ztot += sz[w];
#pragma unroll
            for (int e = 0; e < E; e++) ptot[e] += sp[w][e];
        }
        float aux = 0.0f;
#pragma unroll
        for (int e = 0; e < E; e++) {
            float tpe = 0.5f * (float)g_count[e] / (float)T;
            float ppe = ptot[e] / (float)T;
            aux += tpe * ppe;
        }
        out[OUT_AUX] = (float)E * aux;
        out[OUT_Z]   = ztot / (float)T;
    }
}

// ---------------- launch ----------------
extern "C" void kernel_launch(void* const* d_in, const int* in_sizes, int n_in,
                              void* d_out, int out_size) {
    const float* x  = (const float*)d_in[0];
    const float* rw = (const float*)d_in[1];
    const float* gw = (const float*)d_in[2];
    const float* uw = (const float*)d_in[3];
    const float* dw = (const float*)d_in[4];
    const float* sg = (const float*)d_in[5];
    const float* su = (const float*)d_in[6];
    const float* sd = (const float*)d_in[7];
    float* out = (float*)d_out;

    const int SMEM1 = (2 * BM * ASTR + 4 * BK * BSTR) * 4;   // 73728
    const int SMEM2 = (2 * BM * ASTR + 2 * BK * BSTR) * 4;   // 55296
    cudaFuncSetAttribute(gemm1_kernel, cudaFuncAttributeMaxDynamicSharedMemorySize, SMEM1);
    cudaFuncSetAttribute(gemm2_kernel, cudaFuncAttributeMaxDynamicSharedMemorySize, SMEM2);

    float* xr;  cudaGetSymbolAddress((void**)&xr,  g_xr);
    float* gwr; cudaGetSymbolAddress((void**)&gwr, g_gwr);
    float* uwr; cudaGetSymbolAddress((void**)&uwr, g_uwr);
    float* dwr; cudaGetSymbolAddress((void**)&dwr, g_dwr);
    float* sgr; cudaGetSymbolAddress((void**)&sgr, g_sgr);
    float* sur; cudaGetSymbolAddress((void**)&sur, g_sur);
    float* sdr; cudaGetSymbolAddress((void**)&sdr, g_sdr);

    // prep: tf32 pre-rounding (removes all in-loop cvts)
    round_kernel<<<(T * H / 4 + 255) / 256, 256>>>(x, xr, T * H / 4);
    round_kernel<<<(E * H * I / 4 + 255) / 256, 256>>>(gw, gwr, E * H * I / 4);
    round_kernel<<<(E * H * I / 4 + 255) / 256, 256>>>(uw, uwr, E * H * I / 4);
    round_kernel<<<(E * I * H / 4 + 255) / 256, 256>>>(dw, dwr, E * I * H / 4);
    round_kernel<<<(H * I / 4 + 255) / 256, 256>>>(sg, sgr, H * I / 4);
    round_kernel<<<(H * I / 4 + 255) / 256, 256>>>(su, sur, H * I / 4);
    round_kernel<<<(I * H / 4 + 255) / 256, 256>>>(sd, sdr, I * H / 4);

    init_kernel<<<1, 32>>>();
    zero_routed<<<T * H / 4 / 256, 256>>>(out);
    router_kernel<<<T, 256>>>(x, rw, out + OUT_LOG);

    // fused: experts (z<E) + shared (z==E) in one launch each
    gemm1_kernel<<<dim3(I / BN, T / BM, E + 1), 256, SMEM1>>>();
    gemm2_kernel<<<dim3(H / BN, T / BM, E + 1), 256, SMEM2>>>(out);

    finalize_kernel<<<1, 256>>>(out);
}